// round 2
// baseline (speedup 1.0000x reference)
#include <cuda_runtime.h>
#include <math.h>

// Problem constants
#define B_  512
#define F_  1280
#define H_  2560
#define K_  8
#define E_  9

// GEMM1 tiling
#define BM 128
#define BN 128
#define BK 16
#define TM 8
#define TN 8
// 256 threads = 16x16 thread grid

// Scratch for h = relu(x@W1 + b1): [E, B, H] fp32 = 47.2 MB (static device global; no runtime alloc)
__device__ float g_h[(size_t)E_ * B_ * H_];

__global__ __launch_bounds__(256, 2)
void gemm1_relu_kernel(const float* __restrict__ x,
                       const float* __restrict__ W1,
                       const float* __restrict__ b1)
{
    __shared__ float As[BK][BM];       // [k][m]
    __shared__ float Bs[BK][BN];       // [k][n]

    const int e  = blockIdx.z;
    const int m0 = blockIdx.y * BM;    // batch rows
    const int n0 = blockIdx.x * BN;    // H cols

    const float* __restrict__ A  = x;                              // [B_, F_]
    const float* __restrict__ Bm = W1 + (size_t)e * F_ * H_;       // [F_, H_]

    const int tid = threadIdx.x;       // 0..255
    const int tx  = tid & 15;          // 0..15 -> N
    const int ty  = tid >> 4;          // 0..15 -> M

    float acc[TM][TN];
#pragma unroll
    for (int i = 0; i < TM; i++)
#pragma unroll
        for (int j = 0; j < TN; j++) acc[i][j] = 0.0f;

    for (int k0 = 0; k0 < F_; k0 += BK) {
        // Load A tile: 128 rows x 16 k = 512 float4, 2 per thread
#pragma unroll
        for (int s = 0; s < 2; s++) {
            int i  = tid + s * 256;
            int r  = i >> 2;            // 0..127
            int kq = (i & 3) * 4;       // 0,4,8,12
            float4 v = *(const float4*)&A[(size_t)(m0 + r) * F_ + k0 + kq];
            As[kq + 0][r] = v.x;
            As[kq + 1][r] = v.y;
            As[kq + 2][r] = v.z;
            As[kq + 3][r] = v.w;
        }
        // Load B tile: 16 rows x 128 n = 512 float4, 2 per thread
#pragma unroll
        for (int s = 0; s < 2; s++) {
            int i = tid + s * 256;
            int r = i >> 5;             // 0..15
            int c = (i & 31) * 4;       // 0..124
            *(float4*)&Bs[r][c] = *(const float4*)&Bm[(size_t)(k0 + r) * H_ + n0 + c];
        }
        __syncthreads();

#pragma unroll
        for (int kk = 0; kk < BK; kk++) {
            float a[TM], b[TN];
#pragma unroll
            for (int i = 0; i < TM; i += 4) {
                float4 v = *(const float4*)&As[kk][ty * TM + i];
                a[i + 0] = v.x; a[i + 1] = v.y; a[i + 2] = v.z; a[i + 3] = v.w;
            }
#pragma unroll
            for (int j = 0; j < TN; j += 4) {
                float4 v = *(const float4*)&Bs[kk][tx * TN + j];
                b[j + 0] = v.x; b[j + 1] = v.y; b[j + 2] = v.z; b[j + 3] = v.w;
            }
#pragma unroll
            for (int i = 0; i < TM; i++)
#pragma unroll
                for (int j = 0; j < TN; j++)
                    acc[i][j] = fmaf(a[i], b[j], acc[i][j]);
        }
        __syncthreads();
    }

    // Epilogue: + b1, ReLU, store to g_h[e, b, h]
    const float* __restrict__ bias = b1 + (size_t)e * H_ + n0 + tx * TN;
    float bl[TN];
#pragma unroll
    for (int j = 0; j < TN; j += 4) {
        float4 v = *(const float4*)&bias[j];
        bl[j + 0] = v.x; bl[j + 1] = v.y; bl[j + 2] = v.z; bl[j + 3] = v.w;
    }
    float* __restrict__ hout = g_h + (size_t)e * B_ * H_;
#pragma unroll
    for (int i = 0; i < TM; i++) {
        int brow = m0 + ty * TM + i;
        float* dst = hout + (size_t)brow * H_ + n0 + tx * TN;
#pragma unroll
        for (int j = 0; j < TN; j += 4) {
            float4 v;
            v.x = fmaxf(acc[i][j + 0] + bl[j + 0], 0.0f);
            v.y = fmaxf(acc[i][j + 1] + bl[j + 1], 0.0f);
            v.z = fmaxf(acc[i][j + 2] + bl[j + 2], 0.0f);
            v.w = fmaxf(acc[i][j + 3] + bl[j + 3], 0.0f);
            *(float4*)&dst[j] = v;
        }
    }
}

// One block per batch row b. Computes logits[e,b,:] for all 9 experts,
// softmax per expert, then leaf path products. Writes both outputs.
// Output layout: [0 .. B*73)           leaf_probs [B,73] row-major
//                [B*73 .. B*73+E*B*K)  logits     [E,B,K] row-major
__global__ __launch_bounds__(256)
void tail_kernel(const float* __restrict__ W2,
                 const float* __restrict__ b2,
                 float* __restrict__ out)
{
    const int b   = blockIdx.x;
    const int tid = threadIdx.x;
    const int warp = tid >> 5;
    const int lane = tid & 31;

    __shared__ float hs[H_];
    __shared__ float logits_s[E_][K_];
    __shared__ float probs_s[E_][K_];

    for (int e = 0; e < E_; e++) {
        // load h[e, b, :] (2560 floats = 640 float4) cooperatively
        const float* hrow = g_h + ((size_t)e * B_ + b) * H_;
        for (int i = tid; i < H_ / 4; i += 256) {
            *(float4*)&hs[i * 4] = *(const float4*)&hrow[i * 4];
        }
        __syncthreads();

        if (warp < K_) {
            const int k = warp;
            const float* __restrict__ w2 = W2 + (size_t)e * H_ * K_;
            float sum = 0.0f;
#pragma unroll 4
            for (int i = lane; i < H_; i += 32)
                sum = fmaf(hs[i], w2[(size_t)i * K_ + k], sum);
#pragma unroll
            for (int o = 16; o > 0; o >>= 1)
                sum += __shfl_xor_sync(0xFFFFFFFFu, sum, o);
            if (lane == 0) {
                float lv = sum + b2[e * K_ + k];
                logits_s[e][k] = lv;
                out[(size_t)B_ * 73 + ((size_t)e * B_ + b) * K_ + k] = lv;
            }
        }
        __syncthreads();
    }

    // softmax per expert (9 threads, each over 8 values)
    if (tid < E_) {
        float m = -INFINITY;
#pragma unroll
        for (int k = 0; k < K_; k++) m = fmaxf(m, logits_s[tid][k]);
        float ex[K_];
        float s = 0.0f;
#pragma unroll
        for (int k = 0; k < K_; k++) { ex[k] = expf(logits_s[tid][k] - m); s += ex[k]; }
        float inv = 1.0f / s;
#pragma unroll
        for (int k = 0; k < K_; k++) probs_s[tid][k] = ex[k] * inv;
    }
    __syncthreads();

    // leaf path products: 73 values per batch row
    if (tid < 73) {
        float v;
        if (tid == 0) {
            v = 1.0f;
        } else if (tid < 9) {
            v = probs_s[0][tid - 1];
        } else {
            int t  = tid - 9;
            int c1 = t >> 3;
            int c2 = t & 7;
            v = probs_s[0][c1] * probs_s[1 + c1][c2];
        }
        out[(size_t)b * 73 + tid] = v;
    }
}

extern "C" void kernel_launch(void* const* d_in, const int* in_sizes, int n_in,
                              void* d_out, int out_size)
{
    const float* x  = (const float*)d_in[0];   // [512,1280]
    const float* W1 = (const float*)d_in[1];   // [9,1280,2560]
    const float* b1 = (const float*)d_in[2];   // [9,2560]
    const float* W2 = (const float*)d_in[3];   // [9,2560,8]
    const float* b2 = (const float*)d_in[4];   // [9,8]
    float* out = (float*)d_out;                // 512*73 + 9*512*8 = 74240 floats

    dim3 grid1(H_ / BN, B_ / BM, E_);          // (20, 4, 9)
    gemm1_relu_kernel<<<grid1, 256>>>(x, W1, b1);

    tail_kernel<<<B_, 256>>>(W2, b2, out);
}

// round 4
// speedup vs baseline: 2.0107x; 2.0107x over previous
#include <cuda_runtime.h>
#include <cuda_bf16.h>
#include <math.h>
#include <stdint.h>

#define B_  512
#define F_  1280
#define H_  2560
#define KK  8
#define E_  9

#define CH   32                    // k per chunk
#define NCH  (F_/CH)               // 40
#define SA   40                    // smem row stride (bf16 elems) = 80B, conflict-free
#define BUF_BYTES   (128*SA*2)     // 10240
#define STAGE_BYTES (4*BUF_BYTES)  // 40960: Ah, Al, Bh, Bl
#define AH_OFF 0
#define AL_OFF BUF_BYTES
#define BH_OFF (2*BUF_BYTES)
#define BL_OFF (3*BUF_BYTES)
#define DYN_BYTES (2*STAGE_BYTES)  // 81920; also covers 128*130*4=66560 htile

__device__ __nv_bfloat16 gWh[(size_t)E_*H_*F_];   // W1^T hi  [e][n][k]
__device__ __nv_bfloat16 gWl[(size_t)E_*H_*F_];   // W1^T lo
__device__ __nv_bfloat16 gXh[(size_t)B_*F_];      // x hi [b][k]
__device__ __nv_bfloat16 gXl[(size_t)B_*F_];
__device__ float gPart[(size_t)E_*20*4*B_*KK];    // [e][nb][quarter][b][8]

__device__ __forceinline__ uint32_t smem_u32(const void* p){
    uint32_t a; asm("{ .reg .u64 t; cvta.to.shared.u64 t, %1; cvt.u32.u64 %0, t; }":"=r"(a):"l"(p)); return a;
}
#define CP16(dst,src) asm volatile("cp.async.cg.shared.global [%0], [%1], 16;"::"r"(dst),"l"(src):"memory")
#define LDM4(r,addr) asm volatile("ldmatrix.sync.aligned.m8n8.x4.shared.b16 {%0,%1,%2,%3}, [%4];" \
    : "=r"((r)[0]),"=r"((r)[1]),"=r"((r)[2]),"=r"((r)[3]) : "r"(addr))
__device__ __forceinline__ void mma_bf16(float* c, const uint32_t* a, const uint32_t* b){
    asm volatile("mma.sync.aligned.m16n8k16.row.col.f32.bf16.bf16.f32 "
        "{%0,%1,%2,%3},{%4,%5,%6,%7},{%8,%9},{%0,%1,%2,%3};"
        : "+f"(c[0]),"+f"(c[1]),"+f"(c[2]),"+f"(c[3])
        : "r"(a[0]),"r"(a[1]),"r"(a[2]),"r"(a[3]),"r"(b[0]),"r"(b[1]));
}
__device__ __forceinline__ void split1(float v, unsigned short& h, unsigned short& l){
    __nv_bfloat16 hb = __float2bfloat16(v);
    __nv_bfloat16 lb = __float2bfloat16(v - __bfloat162float(hb));
    h = __bfloat16_as_ushort(hb); l = __bfloat16_as_ushort(lb);
}

// ---- x -> hi/lo bf16, elementwise. grid 640 x 256 over float4s.
__global__ __launch_bounds__(256) void conv_x_kernel(const float* __restrict__ x){
    int i = blockIdx.x*256 + threadIdx.x;          // 163840 float4s
    float4 v = ((const float4*)x)[i];
    ushort4 h, l;
    split1(v.x, h.x, l.x); split1(v.y, h.y, l.y);
    split1(v.z, h.z, l.z); split1(v.w, h.w, l.w);
    ((ushort4*)gXh)[i] = h;
    ((ushort4*)gXl)[i] = l;
}

// ---- W1 [e][k][n] -> W1^T hi/lo [e][n][k]. grid 3600 = e*20(kc)*20(nb), 256 thr.
__global__ __launch_bounds__(256) void conv_w1_kernel(const float* __restrict__ W1){
    __shared__ float s[64][129];
    int tile = blockIdx.x;
    int nb = tile % 20, kc = (tile/20) % 20, e = tile/400;
    const float* src = W1 + ((size_t)e*F_ + (size_t)kc*64)*H_ + (size_t)nb*128;
    for(int i=threadIdx.x; i<64*128; i+=256){
        int kk = i>>7, r = i&127;
        s[kk][r] = src[(size_t)kk*H_ + r];
    }
    __syncthreads();
    int kg = threadIdx.x & 7;
    int rbase = threadIdx.x >> 3;                  // 0..31
#pragma unroll
    for(int u=0; u<4; u++){
        int row = u*32 + rbase;                    // 0..127 (n within tile)
        ushort4 h0,h1,l0,l1;
        split1(s[kg*8+0][row], h0.x, l0.x); split1(s[kg*8+1][row], h0.y, l0.y);
        split1(s[kg*8+2][row], h0.z, l0.z); split1(s[kg*8+3][row], h0.w, l0.w);
        split1(s[kg*8+4][row], h1.x, l1.x); split1(s[kg*8+5][row], h1.y, l1.y);
        split1(s[kg*8+6][row], h1.z, l1.z); split1(s[kg*8+7][row], h1.w, l1.w);
        size_t off = (size_t)e*H_*F_ + (size_t)(nb*128+row)*F_ + kc*64 + kg*8;
        *(ushort4*)(gWh+off) = h0; *(ushort4*)(gWh+off+4) = h1;
        *(ushort4*)(gWl+off) = l0; *(ushort4*)(gWl+off+4) = l1;
    }
}

// ---- GEMM1 (mma.sync bf16 3-pass) + fused bias/ReLU + GEMM2 partials.
// grid (4 mb, 20 nb, 9 e), 512 threads, warp grid 4x4, warp tile 32x32.
__global__ __launch_bounds__(512) void gemm_kernel(const float* __restrict__ W2,
                                                   const float* __restrict__ b1){
    extern __shared__ char dyn[];
    __shared__ float w2s[128*8];
    __shared__ float biass[128];

    const int tid = threadIdx.x, lane = tid & 31, wid = tid >> 5;
    const int warp_m = wid & 3, warp_n = wid >> 2;
    const int m0 = blockIdx.x*128, n0 = blockIdx.y*128, e = blockIdx.z;
    const uint32_t dynU = smem_u32(dyn);

    // W2 tile + bias
    if(tid < 256) ((float4*)w2s)[tid] = ((const float4*)(W2 + ((size_t)e*H_ + n0)*KK))[tid];
    if(tid < 32)  ((float4*)biass)[tid] = ((const float4*)(b1 + (size_t)e*H_ + n0))[tid];

    // cp.async mapping: 512 thr -> 128 rows x 4 segs of 16B per buffer
    const int crow = tid >> 2, cseg = tid & 3;
    const uint32_t dstoff = crow*(SA*2) + cseg*16;
    const __nv_bfloat16* gAh = gXh + (size_t)(m0+crow)*F_ + cseg*8;
    const __nv_bfloat16* gAl = gXl + (size_t)(m0+crow)*F_ + cseg*8;
    const __nv_bfloat16* gBh = gWh + ((size_t)e*H_ + n0 + crow)*F_ + cseg*8;
    const __nv_bfloat16* gBl = gWl + ((size_t)e*H_ + n0 + crow)*F_ + cseg*8;

#define ISSUE(c) do{ \
    uint32_t st_ = dynU + ((c)&1)*STAGE_BYTES; int ko_ = (c)*CH; \
    CP16(st_+AH_OFF+dstoff, gAh+ko_); CP16(st_+AL_OFF+dstoff, gAl+ko_); \
    CP16(st_+BH_OFF+dstoff, gBh+ko_); CP16(st_+BL_OFF+dstoff, gBl+ko_); \
    asm volatile("cp.async.commit_group;":::"memory"); }while(0)

    float acc[2][4][4];
#pragma unroll
    for(int a=0;a<2;a++)
#pragma unroll
    for(int b=0;b<4;b++)
#pragma unroll
    for(int d=0;d<4;d++) acc[a][b][d]=0.f;

    ISSUE(0);
    for(int c=0;c<NCH;c++){
        if(c+1<NCH){ ISSUE(c+1); asm volatile("cp.async.wait_group 1;":::"memory"); }
        else       {              asm volatile("cp.async.wait_group 0;":::"memory"); }
        __syncthreads();
        const uint32_t st = dynU + (c&1)*STAGE_BYTES;
#pragma unroll
        for(int ks=0; ks<2; ks++){
            uint32_t ah[2][4], al[2][4], bh[2][4], bl[2][4];
            // A: lanes 0-15 rows0-15@k0, 16-31 rows0-15@k0+8
            const int arow = warp_m*32 + (lane & 15);
            const int akoff = (ks*16 + ((lane>>4)<<3))*2;
#pragma unroll
            for(int mi=0; mi<2; mi++){
                uint32_t ad = st + AH_OFF + (uint32_t)(arow + mi*16)*(SA*2) + akoff;
                LDM4(ah[mi], ad);
                LDM4(al[mi], ad + BUF_BYTES);
            }
            // B: lanes 0-7 rows0-7@k0, 8-15 rows0-7@k0+8, 16-23 rows8-15@k0, 24-31 rows8-15@k0+8
            const int brow = warp_n*32 + ((lane>>4)&1)*8 + (lane&7);
            const int bkoff = (ks*16 + (((lane>>3)&1)<<3))*2;
#pragma unroll
            for(int nip=0; nip<2; nip++){
                uint32_t bd = st + BH_OFF + (uint32_t)(brow + nip*16)*(SA*2) + bkoff;
                LDM4(bh[nip], bd);
                LDM4(bl[nip], bd + BUF_BYTES);
            }
#pragma unroll
            for(int mi=0; mi<2; mi++)
#pragma unroll
            for(int ni=0; ni<4; ni++){
                const uint32_t* bph = &bh[ni>>1][(ni&1)*2];
                const uint32_t* bpl = &bl[ni>>1][(ni&1)*2];
                mma_bf16(acc[mi][ni], ah[mi], bph);   // hi*hi
                mma_bf16(acc[mi][ni], al[mi], bph);   // lo*hi
                mma_bf16(acc[mi][ni], ah[mi], bpl);   // hi*lo
            }
        }
        __syncthreads();
    }
#undef ISSUE

    // epilogue: bias + ReLU -> htile (reuse pipeline smem), then GEMM2 partials
    float* ht = (float*)dyn;                          // [128][130]
    const int g = lane >> 2, tg2 = (lane & 3)*2;
#pragma unroll
    for(int mi=0; mi<2; mi++){
        int r0 = warp_m*32 + mi*16 + g;
#pragma unroll
        for(int ni=0; ni<4; ni++){
            int c0 = warp_n*32 + ni*8 + tg2;
            float2 v0, v1;
            v0.x = fmaxf(acc[mi][ni][0] + biass[c0],   0.f);
            v0.y = fmaxf(acc[mi][ni][1] + biass[c0+1], 0.f);
            v1.x = fmaxf(acc[mi][ni][2] + biass[c0],   0.f);
            v1.y = fmaxf(acc[mi][ni][3] + biass[c0+1], 0.f);
            *(float2*)&ht[(size_t)r0*130 + c0]     = v0;
            *(float2*)&ht[(size_t)(r0+8)*130 + c0] = v1;
        }
    }
    __syncthreads();
    {
        const int row = tid >> 2, q = tid & 3;        // 128 rows x 4 quarters of 32 cols
        const float* hp = &ht[(size_t)row*130 + q*32];
        const float* wp = &w2s[q*32*8];
        float pl[8];
#pragma unroll
        for(int k=0;k<8;k++) pl[k]=0.f;
#pragma unroll
        for(int cc=0; cc<32; cc++){
            float h = hp[cc];
            const float4* w4 = (const float4*)&wp[cc*8];
            float4 wa = w4[0], wb = w4[1];
            pl[0]=fmaf(h,wa.x,pl[0]); pl[1]=fmaf(h,wa.y,pl[1]);
            pl[2]=fmaf(h,wa.z,pl[2]); pl[3]=fmaf(h,wa.w,pl[3]);
            pl[4]=fmaf(h,wb.x,pl[4]); pl[5]=fmaf(h,wb.y,pl[5]);
            pl[6]=fmaf(h,wb.z,pl[6]); pl[7]=fmaf(h,wb.w,pl[7]);
        }
        float* dst = gPart + (((((size_t)e*20 + blockIdx.y)*4 + q)*B_) + (m0+row))*KK;
        *(float4*)dst     = make_float4(pl[0],pl[1],pl[2],pl[3]);
        *(float4*)(dst+4) = make_float4(pl[4],pl[5],pl[6],pl[7]);
    }
}

// ---- tail: sum 80 partials per (e,k), +b2, softmax, path products
__global__ __launch_bounds__(256) void tail_kernel(const float* __restrict__ b2,
                                                   float* __restrict__ out){
    const int b = blockIdx.x, tid = threadIdx.x;
    __shared__ float part[720][8];
    __shared__ float logits_s[9][8];
    __shared__ float probs_s[9][8];
    for(int t=tid; t<720; t+=256){
        const float4* src = (const float4*)(gPart + ((size_t)t*B_ + b)*KK);
        *(float4*)&part[t][0] = src[0];
        *(float4*)&part[t][4] = src[1];
    }
    __syncthreads();
    if(tid < 72){
        int e = tid>>3, k = tid&7;
        float s = 0.f;
#pragma unroll
        for(int j=0;j<80;j++) s += part[e*80+j][k];
        float lv = s + b2[tid];
        logits_s[e][k] = lv;
        out[(size_t)B_*73 + ((size_t)e*B_ + b)*KK + k] = lv;
    }
    __syncthreads();
    if(tid < 9){
        float m = -INFINITY;
#pragma unroll
        for(int k=0;k<8;k++) m = fmaxf(m, logits_s[tid][k]);
        float ex[8], s = 0.f;
#pragma unroll
        for(int k=0;k<8;k++){ ex[k] = expf(logits_s[tid][k]-m); s += ex[k]; }
        float inv = 1.f/s;
#pragma unroll
        for(int k=0;k<8;k++) probs_s[tid][k] = ex[k]*inv;
    }
    __syncthreads();
    if(tid < 73){
        float v;
        if(tid==0) v = 1.f;
        else if(tid<9) v = probs_s[0][tid-1];
        else { int t = tid-9; v = probs_s[0][t>>3]*probs_s[1+(t>>3)][t&7]; }
        out[(size_t)b*73 + tid] = v;
    }
}

extern "C" void kernel_launch(void* const* d_in, const int* in_sizes, int n_in,
                              void* d_out, int out_size){
    const float* x  = (const float*)d_in[0];
    const float* W1 = (const float*)d_in[1];
    const float* b1 = (const float*)d_in[2];
    const float* W2 = (const float*)d_in[3];
    const float* b2 = (const float*)d_in[4];
    float* out = (float*)d_out;

    cudaFuncSetAttribute(gemm_kernel, cudaFuncAttributeMaxDynamicSharedMemorySize, DYN_BYTES);

    conv_x_kernel<<<640, 256>>>(x);
    conv_w1_kernel<<<3600, 256>>>(W1);
    dim3 grid(4, 20, 9);
    gemm_kernel<<<grid, 512, DYN_BYTES>>>(W2, b1);
    tail_kernel<<<B_, 256>>>(b2, out);
}

// round 5
// speedup vs baseline: 3.7736x; 1.8768x over previous
#include <cuda_runtime.h>
#include <cuda_fp16.h>
#include <math.h>
#include <stdint.h>

#define B_  512
#define F_  1280
#define H_  2560
#define KK  8
#define E_  9

#define CH   64                    // k per chunk
#define NCH  (F_/CH)               // 20
#define SAE  72                    // padded row stride (fp16 elems) -> 144B
#define ROWB (SAE*2)               // 144
#define BUF_BYTES   (128*ROWB)     // 18432
#define STAGE_BYTES (2*BUF_BYTES)  // A, B
#define A_OFF 0
#define B_OFF BUF_BYTES
#define DYN_BYTES (2*STAGE_BYTES)  // 73728 (also covers htile 128*130*4 = 66560)

__device__ __half gW[(size_t)E_*H_*F_];   // W1^T fp16 [e][n][k]
__device__ __half gX[(size_t)B_*F_];      // x fp16 [b][k]
__device__ float gPart[(size_t)E_*20*B_*KK];  // [e][nb][b][8]

__device__ __forceinline__ uint32_t smem_u32(const void* p){
    uint32_t a; asm("{ .reg .u64 t; cvta.to.shared.u64 t, %1; cvt.u32.u64 %0, t; }":"=r"(a):"l"(p)); return a;
}
#define CP16(dst,src) asm volatile("cp.async.cg.shared.global [%0], [%1], 16;"::"r"(dst),"l"(src):"memory")
#define LDM4(r,addr) asm volatile("ldmatrix.sync.aligned.m8n8.x4.shared.b16 {%0,%1,%2,%3}, [%4];" \
    : "=r"((r)[0]),"=r"((r)[1]),"=r"((r)[2]),"=r"((r)[3]) : "r"(addr))
__device__ __forceinline__ void mma_f16(float* c, const uint32_t* a, const uint32_t* b){
    asm volatile("mma.sync.aligned.m16n8k16.row.col.f32.f16.f16.f32 "
        "{%0,%1,%2,%3},{%4,%5,%6,%7},{%8,%9},{%0,%1,%2,%3};"
        : "+f"(c[0]),"+f"(c[1]),"+f"(c[2]),"+f"(c[3])
        : "r"(a[0]),"r"(a[1]),"r"(a[2]),"r"(a[3]),"r"(b[0]),"r"(b[1]));
}

// ---- x -> fp16. 163840 float4s.
__global__ __launch_bounds__(256) void conv_x_kernel(const float* __restrict__ x){
    int i = blockIdx.x*256 + threadIdx.x;
    float4 v = ((const float4*)x)[i];
    ushort4 h;
    h.x = __half_as_ushort(__float2half(v.x));
    h.y = __half_as_ushort(__float2half(v.y));
    h.z = __half_as_ushort(__float2half(v.z));
    h.w = __half_as_ushort(__float2half(v.w));
    ((ushort4*)gX)[i] = h;
}

// ---- W1 [e][k][n] -> W1^T fp16 [e][n][k]. grid 3600 = e*20(kc)*20(nb).
__global__ __launch_bounds__(256) void conv_w1_kernel(const float* __restrict__ W1){
    __shared__ float s[64][129];
    int tile = blockIdx.x;
    int nb = tile % 20, kc = (tile/20) % 20, e = tile/400;
    const float* src = W1 + ((size_t)e*F_ + (size_t)kc*64)*H_ + (size_t)nb*128;
    for(int i=threadIdx.x; i<64*128; i+=256){
        int kk = i>>7, r = i&127;
        s[kk][r] = src[(size_t)kk*H_ + r];
    }
    __syncthreads();
    int kg = threadIdx.x & 7;
    int rbase = threadIdx.x >> 3;
#pragma unroll
    for(int u=0; u<4; u++){
        int row = u*32 + rbase;
        ushort4 h0, h1;
        h0.x=__half_as_ushort(__float2half(s[kg*8+0][row]));
        h0.y=__half_as_ushort(__float2half(s[kg*8+1][row]));
        h0.z=__half_as_ushort(__float2half(s[kg*8+2][row]));
        h0.w=__half_as_ushort(__float2half(s[kg*8+3][row]));
        h1.x=__half_as_ushort(__float2half(s[kg*8+4][row]));
        h1.y=__half_as_ushort(__float2half(s[kg*8+5][row]));
        h1.z=__half_as_ushort(__float2half(s[kg*8+6][row]));
        h1.w=__half_as_ushort(__float2half(s[kg*8+7][row]));
        size_t off = (size_t)e*H_*F_ + (size_t)(nb*128+row)*F_ + kc*64 + kg*8;
        *(ushort4*)(gW+off)   = h0;
        *(ushort4*)(gW+off+4) = h1;
    }
}

// ---- GEMM1 (mma.sync fp16 single-pass) + fused bias/ReLU + GEMM2 partials.
// grid (4 mb, 20 nb, 9 e), 512 threads, warp grid 4x4, warp tile 32x32.
__global__ __launch_bounds__(512) void gemm_kernel(const float* __restrict__ W2,
                                                   const float* __restrict__ b1){
    extern __shared__ char dyn[];
    __shared__ float w2s[128*8];
    __shared__ float biass[128];

    const int tid = threadIdx.x, lane = tid & 31, wid = tid >> 5;
    const int warp_m = wid & 3, warp_n = wid >> 2;
    const int m0 = blockIdx.x*128, n0 = blockIdx.y*128, e = blockIdx.z;
    const uint32_t dynU = smem_u32(dyn);

    if(tid < 256) ((float4*)w2s)[tid] = ((const float4*)(W2 + ((size_t)e*H_ + n0)*KK))[tid];
    if(tid < 32)  ((float4*)biass)[tid] = ((const float4*)(b1 + (size_t)e*H_ + n0))[tid];

    // cp.async: per buffer 128 rows x 8 segs of 16B -> 1024 tasks, 2 per thread
    const int r0c = tid >> 3, s0c = tid & 7;          // lin = tid
    const int r1c = (tid+512) >> 3, s1c = tid & 7;    // lin = tid+512
    const __half* gA = gX + (size_t)m0*F_;
    const __half* gB = gW + ((size_t)e*H_ + n0)*F_;

#define ISSUE(c) do{ \
    uint32_t st_ = dynU + ((c)&1)*STAGE_BYTES; int ko_ = (c)*CH; \
    CP16(st_+A_OFF + r0c*ROWB + s0c*16, gA + (size_t)r0c*F_ + ko_ + s0c*8); \
    CP16(st_+A_OFF + r1c*ROWB + s1c*16, gA + (size_t)r1c*F_ + ko_ + s1c*8); \
    CP16(st_+B_OFF + r0c*ROWB + s0c*16, gB + (size_t)r0c*F_ + ko_ + s0c*8); \
    CP16(st_+B_OFF + r1c*ROWB + s1c*16, gB + (size_t)r1c*F_ + ko_ + s1c*8); \
    asm volatile("cp.async.commit_group;":::"memory"); }while(0)

    float acc[2][4][4];
#pragma unroll
    for(int a=0;a<2;a++)
#pragma unroll
    for(int b=0;b<4;b++)
#pragma unroll
    for(int d=0;d<4;d++) acc[a][b][d]=0.f;

    ISSUE(0);
    for(int c=0;c<NCH;c++){
        if(c+1<NCH){ ISSUE(c+1); asm volatile("cp.async.wait_group 1;":::"memory"); }
        else       {              asm volatile("cp.async.wait_group 0;":::"memory"); }
        __syncthreads();
        const uint32_t st = dynU + (c&1)*STAGE_BYTES;
#pragma unroll
        for(int ks=0; ks<4; ks++){
            uint32_t ah[2][4], bh[2][4];
            const int arow = warp_m*32 + (lane & 15);
            const int akoff = (ks*16 + ((lane>>4)<<3))*2;
#pragma unroll
            for(int mi=0; mi<2; mi++)
                LDM4(ah[mi], st + A_OFF + (uint32_t)(arow + mi*16)*ROWB + akoff);
            const int brow = warp_n*32 + ((lane>>4)&1)*8 + (lane&7);
            const int bkoff = (ks*16 + (((lane>>3)&1)<<3))*2;
#pragma unroll
            for(int nip=0; nip<2; nip++)
                LDM4(bh[nip], st + B_OFF + (uint32_t)(brow + nip*16)*ROWB + bkoff);
#pragma unroll
            for(int mi=0; mi<2; mi++)
#pragma unroll
            for(int ni=0; ni<4; ni++)
                mma_f16(acc[mi][ni], ah[mi], &bh[ni>>1][(ni&1)*2]);
        }
        __syncthreads();
    }
#undef ISSUE

    // epilogue: bias + ReLU -> htile, then GEMM2 partials, reduce quarters via shfl
    float* ht = (float*)dyn;                          // [128][130]
    const int g = lane >> 2, tg2 = (lane & 3)*2;
#pragma unroll
    for(int mi=0; mi<2; mi++){
        int r0 = warp_m*32 + mi*16 + g;
#pragma unroll
        for(int ni=0; ni<4; ni++){
            int c0 = warp_n*32 + ni*8 + tg2;
            float2 v0, v1;
            v0.x = fmaxf(acc[mi][ni][0] + biass[c0],   0.f);
            v0.y = fmaxf(acc[mi][ni][1] + biass[c0+1], 0.f);
            v1.x = fmaxf(acc[mi][ni][2] + biass[c0],   0.f);
            v1.y = fmaxf(acc[mi][ni][3] + biass[c0+1], 0.f);
            *(float2*)&ht[(size_t)r0*130 + c0]     = v0;
            *(float2*)&ht[(size_t)(r0+8)*130 + c0] = v1;
        }
    }
    __syncthreads();
    {
        const int row = tid >> 2, q = tid & 3;        // 4-lane groups share a row
        const float* hp = &ht[(size_t)row*130 + q*32];
        const float* wp = &w2s[q*32*8];
        float pl[8];
#pragma unroll
        for(int k=0;k<8;k++) pl[k]=0.f;
#pragma unroll
        for(int cc=0; cc<32; cc++){
            int cr = (cc + q*8) & 31;                 // rotate to break bank conflicts
            float h = hp[cr];
            const float4* w4 = (const float4*)&wp[cr*8];
            float4 wa = w4[0], wb = w4[1];
            pl[0]=fmaf(h,wa.x,pl[0]); pl[1]=fmaf(h,wa.y,pl[1]);
            pl[2]=fmaf(h,wa.z,pl[2]); pl[3]=fmaf(h,wa.w,pl[3]);
            pl[4]=fmaf(h,wb.x,pl[4]); pl[5]=fmaf(h,wb.y,pl[5]);
            pl[6]=fmaf(h,wb.z,pl[6]); pl[7]=fmaf(h,wb.w,pl[7]);
        }
        // reduce across q (lanes q=0..3 of each 4-lane group)
#pragma unroll
        for(int o=1; o<=2; o<<=1)
#pragma unroll
            for(int k=0;k<8;k++) pl[k] += __shfl_xor_sync(0xFFFFFFFFu, pl[k], o);
        // each lane writes its pair: k = 2q, 2q+1
        float* dst = gPart + (((size_t)e*20 + blockIdx.y)*B_ + (m0+row))*KK + q*2;
        *(float2*)dst = make_float2(pl[q*2], pl[q*2+1]);
    }
}

// ---- tail: sum 20 partials per (e,k), +b2, softmax, path products
__global__ __launch_bounds__(256) void tail_kernel(const float* __restrict__ b2,
                                                   float* __restrict__ out){
    const int b = blockIdx.x, tid = threadIdx.x;
    __shared__ float part[180][8];
    __shared__ float logits_s[9][8];
    __shared__ float probs_s[9][8];
    for(int t=tid; t<180; t+=256){
        const float4* src = (const float4*)(gPart + ((size_t)t*B_ + b)*KK);
        *(float4*)&part[t][0] = src[0];
        *(float4*)&part[t][4] = src[1];
    }
    __syncthreads();
    if(tid < 72){
        int e = tid>>3, k = tid&7;
        float s = 0.f;
#pragma unroll
        for(int j=0;j<20;j++) s += part[e*20+j][k];
        float lv = s + b2[tid];
        logits_s[e][k] = lv;
        out[(size_t)B_*73 + ((size_t)e*B_ + b)*KK + k] = lv;
    }
    __syncthreads();
    if(tid < 9){
        float m = -INFINITY;
#pragma unroll
        for(int k=0;k<8;k++) m = fmaxf(m, logits_s[tid][k]);
        float ex[8], s = 0.f;
#pragma unroll
        for(int k=0;k<8;k++){ ex[k] = expf(logits_s[tid][k]-m); s += ex[k]; }
        float inv = 1.f/s;
#pragma unroll
        for(int k=0;k<8;k++) probs_s[tid][k] = ex[k]*inv;
    }
    __syncthreads();
    if(tid < 73){
        float v;
        if(tid==0) v = 1.f;
        else if(tid<9) v = probs_s[0][tid-1];
        else { int t = tid-9; v = probs_s[0][t>>3]*probs_s[1+(t>>3)][t&7]; }
        out[(size_t)b*73 + tid] = v;
    }
}

extern "C" void kernel_launch(void* const* d_in, const int* in_sizes, int n_in,
                              void* d_out, int out_size){
    const float* x  = (const float*)d_in[0];
    const float* W1 = (const float*)d_in[1];
    const float* b1 = (const float*)d_in[2];
    const float* W2 = (const float*)d_in[3];
    const float* b2 = (const float*)d_in[4];
    float* out = (float*)d_out;

    cudaFuncSetAttribute(gemm_kernel, cudaFuncAttributeMaxDynamicSharedMemorySize, DYN_BYTES);

    conv_x_kernel<<<640, 256>>>(x);
    conv_w1_kernel<<<3600, 256>>>(W1);
    dim3 grid(4, 20, 9);
    gemm_kernel<<<grid, 512, DYN_BYTES>>>(W2, b1);
    tail_kernel<<<B_, 256>>>(b2, out);
}

// round 6
// speedup vs baseline: 4.1921x; 1.1109x over previous
#include <cuda_runtime.h>
#include <cuda_fp16.h>
#include <math.h>
#include <stdint.h>

#define B_  512
#define F_  1280
#define H_  2560
#define KK  8
#define E_  9

#define CH   64                    // k per chunk
#define NCH  (F_/CH)               // 20
#define SAE  72                    // padded row stride (fp16 elems) -> 144B
#define ROWB (SAE*2)               // 144
#define BUF_BYTES   (128*ROWB)     // 18432
#define STAGE_BYTES (2*BUF_BYTES)  // A, B = 36864
#define A_OFF 0
#define B_OFF BUF_BYTES
#define NSTG 3
#define DYN_BYTES (NSTG*STAGE_BYTES)  // 110592 (covers htile 128*130*4 = 66560)

__device__ __half gW[(size_t)E_*H_*F_];       // W1^T fp16 [e][n][k]
__device__ __half gX[(size_t)B_*F_];          // x fp16 [b][k]
__device__ float gPart[(size_t)E_*20*B_*KK];  // [e][nb][b][8]

__device__ __forceinline__ uint32_t smem_u32(const void* p){
    uint32_t a; asm("{ .reg .u64 t; cvta.to.shared.u64 t, %1; cvt.u32.u64 %0, t; }":"=r"(a):"l"(p)); return a;
}
#define CP16(dst,src) asm volatile("cp.async.cg.shared.global [%0], [%1], 16;"::"r"(dst),"l"(src):"memory")
#define LDM4(r,addr) asm volatile("ldmatrix.sync.aligned.m8n8.x4.shared.b16 {%0,%1,%2,%3}, [%4];" \
    : "=r"((r)[0]),"=r"((r)[1]),"=r"((r)[2]),"=r"((r)[3]) : "r"(addr))
__device__ __forceinline__ void mma_f16(float* c, const uint32_t* a, const uint32_t* b){
    asm volatile("mma.sync.aligned.m16n8k16.row.col.f32.f16.f16.f32 "
        "{%0,%1,%2,%3},{%4,%5,%6,%7},{%8,%9},{%0,%1,%2,%3};"
        : "+f"(c[0]),"+f"(c[1]),"+f"(c[2]),"+f"(c[3])
        : "r"(a[0]),"r"(a[1]),"r"(a[2]),"r"(a[3]),"r"(b[0]),"r"(b[1]));
}
__device__ __forceinline__ uint32_t pack2(float a, float b){
    __half2 h = __floats2half2_rn(a, b);
    return *reinterpret_cast<uint32_t*>(&h);
}

// ---- x -> fp16, packed converts. 163840 float4s.
__global__ __launch_bounds__(256) void conv_x_kernel(const float* __restrict__ x){
    int i = blockIdx.x*256 + threadIdx.x;
    float4 v = ((const float4*)x)[i];
    uint2 o;
    o.x = pack2(v.x, v.y);
    o.y = pack2(v.z, v.w);
    ((uint2*)gX)[i] = o;
}

// ---- W1 [e][k][n] -> W1^T fp16 [e][n][k], packed converts. grid 3600.
__global__ __launch_bounds__(256) void conv_w1_kernel(const float* __restrict__ W1){
    __shared__ float s[64][129];
    int tile = blockIdx.x;
    int nb = tile % 20, kc = (tile/20) % 20, e = tile/400;
    const float* src = W1 + ((size_t)e*F_ + (size_t)kc*64)*H_ + (size_t)nb*128;
    for(int i=threadIdx.x; i<64*128; i+=256){
        int kk = i>>7, r = i&127;
        s[kk][r] = src[(size_t)kk*H_ + r];
    }
    __syncthreads();
    int kg = threadIdx.x & 7;
    int rbase = threadIdx.x >> 3;
#pragma unroll
    for(int u=0; u<4; u++){
        int row = u*32 + rbase;
        uint4 o;
        o.x = pack2(s[kg*8+0][row], s[kg*8+1][row]);
        o.y = pack2(s[kg*8+2][row], s[kg*8+3][row]);
        o.z = pack2(s[kg*8+4][row], s[kg*8+5][row]);
        o.w = pack2(s[kg*8+6][row], s[kg*8+7][row]);
        size_t off = (size_t)e*H_*F_ + (size_t)(nb*128+row)*F_ + kc*64 + kg*8;
        *(uint4*)(gW+off) = o;
    }
}

// ---- GEMM1 (fp16 mma.sync) + fused bias/ReLU + GEMM2 partials.
// grid (4 mb, 20 nb, 9 e), 512 threads, warp grid 4x4, warp tile 32x32.
// 3-stage cp.async pipeline, one __syncthreads per chunk.
__global__ __launch_bounds__(512) void gemm_kernel(const float* __restrict__ W2,
                                                   const float* __restrict__ b1){
    extern __shared__ char dyn[];
    __shared__ float w2s[128*8];
    __shared__ float biass[128];

    const int tid = threadIdx.x, lane = tid & 31, wid = tid >> 5;
    const int warp_m = wid & 3, warp_n = wid >> 2;
    const int m0 = blockIdx.x*128, n0 = blockIdx.y*128, e = blockIdx.z;
    const uint32_t dynU = smem_u32(dyn);

    if(tid < 256) ((float4*)w2s)[tid] = ((const float4*)(W2 + ((size_t)e*H_ + n0)*KK))[tid];
    if(tid < 32)  ((float4*)biass)[tid] = ((const float4*)(b1 + (size_t)e*H_ + n0))[tid];

    // cp.async mapping: per buffer 128 rows x 8 segs of 16B = 1024 tasks, 2/thread
    const int r0c = tid >> 3, s0c = tid & 7;
    const int r1c = (tid+512) >> 3;
    const __half* gA = gX + (size_t)m0*F_;
    const __half* gB = gW + ((size_t)e*H_ + n0)*F_;
    const uint32_t d0 = r0c*ROWB + s0c*16;
    const uint32_t d1 = r1c*ROWB + s0c*16;
    const size_t gAo0 = (size_t)r0c*F_ + s0c*8, gAo1 = (size_t)r1c*F_ + s0c*8;

    uint32_t stB[NSTG];
#pragma unroll
    for(int s=0;s<NSTG;s++) stB[s] = dynU + s*STAGE_BYTES;

#define ISSUE(c) do{ \
    uint32_t st_ = stB[(c)%NSTG]; int ko_ = (c)*CH; \
    CP16(st_+A_OFF+d0, gA + gAo0 + ko_); \
    CP16(st_+A_OFF+d1, gA + gAo1 + ko_); \
    CP16(st_+B_OFF+d0, gB + gAo0 + ko_); \
    CP16(st_+B_OFF+d1, gB + gAo1 + ko_); \
    asm volatile("cp.async.commit_group;":::"memory"); }while(0)

    // precomputed ldmatrix bases (per thread, stage-relative)
    const uint32_t aBase = A_OFF + (uint32_t)(warp_m*32 + (lane & 15))*ROWB + (((lane>>4)<<3))*2;
    const uint32_t bBase = B_OFF + (uint32_t)(warp_n*32 + ((lane>>4)&1)*8 + (lane&7))*ROWB + ((((lane>>3)&1)<<3))*2;

    float acc[2][4][4];
#pragma unroll
    for(int a=0;a<2;a++)
#pragma unroll
    for(int b=0;b<4;b++)
#pragma unroll
    for(int d=0;d<4;d++) acc[a][b][d]=0.f;

    ISSUE(0); ISSUE(1);
    for(int c=0;c<NCH;c++){
        asm volatile("cp.async.wait_group 1;":::"memory");
        __syncthreads();
        if(c+2<NCH) ISSUE(c+2);
        const uint32_t st = stB[c%NSTG];
        const uint32_t ab = st + aBase, bb = st + bBase;
#pragma unroll
        for(int ks=0; ks<4; ks++){
            uint32_t ah[2][4], bh[2][4];
#pragma unroll
            for(int mi=0; mi<2; mi++)
                LDM4(ah[mi], ab + mi*16*ROWB + ks*32);
#pragma unroll
            for(int nip=0; nip<2; nip++)
                LDM4(bh[nip], bb + nip*16*ROWB + ks*32);
#pragma unroll
            for(int mi=0; mi<2; mi++)
#pragma unroll
            for(int ni=0; ni<4; ni++)
                mma_f16(acc[mi][ni], ah[mi], &bh[ni>>1][(ni&1)*2]);
        }
    }
#undef ISSUE
    __syncthreads();

    // epilogue: bias + ReLU -> htile, then GEMM2 partials, reduce quarters via shfl
    float* ht = (float*)dyn;                          // [128][130]
    const int g = lane >> 2, tg2 = (lane & 3)*2;
#pragma unroll
    for(int mi=0; mi<2; mi++){
        int r0 = warp_m*32 + mi*16 + g;
#pragma unroll
        for(int ni=0; ni<4; ni++){
            int c0 = warp_n*32 + ni*8 + tg2;
            float2 v0, v1;
            v0.x = fmaxf(acc[mi][ni][0] + biass[c0],   0.f);
            v0.y = fmaxf(acc[mi][ni][1] + biass[c0+1], 0.f);
            v1.x = fmaxf(acc[mi][ni][2] + biass[c0],   0.f);
            v1.y = fmaxf(acc[mi][ni][3] + biass[c0+1], 0.f);
            *(float2*)&ht[(size_t)r0*130 + c0]     = v0;
            *(float2*)&ht[(size_t)(r0+8)*130 + c0] = v1;
        }
    }
    __syncthreads();
    {
        const int row = tid >> 2, q = tid & 3;
        const float* hp = &ht[(size_t)row*130 + q*32];
        const float* wp = &w2s[q*32*8];
        float pl[8];
#pragma unroll
        for(int k=0;k<8;k++) pl[k]=0.f;
#pragma unroll
        for(int cc=0; cc<32; cc++){
            int cr = (cc + q*8) & 31;
            float h = hp[cr];
            const float4* w4 = (const float4*)&wp[cr*8];
            float4 wa = w4[0], wb = w4[1];
            pl[0]=fmaf(h,wa.x,pl[0]); pl[1]=fmaf(h,wa.y,pl[1]);
            pl[2]=fmaf(h,wa.z,pl[2]); pl[3]=fmaf(h,wa.w,pl[3]);
            pl[4]=fmaf(h,wb.x,pl[4]); pl[5]=fmaf(h,wb.y,pl[5]);
            pl[6]=fmaf(h,wb.z,pl[6]); pl[7]=fmaf(h,wb.w,pl[7]);
        }
#pragma unroll
        for(int o=1; o<=2; o<<=1)
#pragma unroll
            for(int k=0;k<8;k++) pl[k] += __shfl_xor_sync(0xFFFFFFFFu, pl[k], o);
        float* dst = gPart + (((size_t)e*20 + blockIdx.y)*B_ + (m0+row))*KK + q*2;
        *(float2*)dst = make_float2(pl[q*2], pl[q*2+1]);
    }
}

// ---- tail: sum 20 partials per (e,k), +b2, softmax, path products
__global__ __launch_bounds__(256) void tail_kernel(const float* __restrict__ b2,
                                                   float* __restrict__ out){
    const int b = blockIdx.x, tid = threadIdx.x;
    __shared__ float part[180][8];
    __shared__ float logits_s[9][8];
    __shared__ float probs_s[9][8];
    for(int t=tid; t<180; t+=256){
        const float4* src = (const float4*)(gPart + ((size_t)t*B_ + b)*KK);
        *(float4*)&part[t][0] = src[0];
        *(float4*)&part[t][4] = src[1];
    }
    __syncthreads();
    if(tid < 72){
        int e = tid>>3, k = tid&7;
        float s = 0.f;
#pragma unroll
        for(int j=0;j<20;j++) s += part[e*20+j][k];
        float lv = s + b2[tid];
        logits_s[e][k] = lv;
        out[(size_t)B_*73 + ((size_t)e*B_ + b)*KK + k] = lv;
    }
    __syncthreads();
    if(tid < 9){
        float m = -INFINITY;
#pragma unroll
        for(int k=0;k<8;k++) m = fmaxf(m, logits_s[tid][k]);
        float ex[8], s = 0.f;
#pragma unroll
        for(int k=0;k<8;k++){ ex[k] = expf(logits_s[tid][k]-m); s += ex[k]; }
        float inv = 1.f/s;
#pragma unroll
        for(int k=0;k<8;k++) probs_s[tid][k] = ex[k]*inv;
    }
    __syncthreads();
    if(tid < 73){
        float v;
        if(tid==0) v = 1.f;
        else if(tid<9) v = probs_s[0][tid-1];
        else { int t = tid-9; v = probs_s[0][t>>3]*probs_s[1+(t>>3)][t&7]; }
        out[(size_t)b*73 + tid] = v;
    }
}

extern "C" void kernel_launch(void* const* d_in, const int* in_sizes, int n_in,
                              void* d_out, int out_size){
    const float* x  = (const float*)d_in[0];
    const float* W1 = (const float*)d_in[1];
    const float* b1 = (const float*)d_in[2];
    const float* W2 = (const float*)d_in[3];
    const float* b2 = (const float*)d_in[4];
    float* out = (float*)d_out;

    cudaFuncSetAttribute(gemm_kernel, cudaFuncAttributeMaxDynamicSharedMemorySize, DYN_BYTES);

    conv_x_kernel<<<640, 256>>>(x);
    conv_w1_kernel<<<3600, 256>>>(W1);
    dim3 grid(4, 20, 9);
    gemm_kernel<<<grid, 512, DYN_BYTES>>>(W2, b1);
    tail_kernel<<<B_, 256>>>(b2, out);
}

// round 8
// speedup vs baseline: 4.6395x; 1.1067x over previous
#include <cuda_runtime.h>
#include <cuda_fp16.h>
#include <math.h>
#include <stdint.h>

#define B_  512
#define F_  1280
#define H_  2560
#define KK  8
#define E_  9

#define CH   64                     // k per chunk
#define NCH  (F_/CH)                // 20
#define SAE  72                     // padded row stride (fp16) -> 144B
#define ROWB (SAE*2)                // 144
#define ABUF_BYTES (256*ROWB)       // 36864
#define BBUF_BYTES (128*ROWB)       // 18432
#define STAGE_BYTES (ABUF_BYTES+BBUF_BYTES)  // 55296
#define A_OFF 0
#define B_OFF ABUF_BYTES
#define NSTG 3
#define DYN_BYTES (NSTG*STAGE_BYTES)  // 165888 (covers htile 256*130*4 = 133120)
#define HTS 130                     // htile row stride (floats): EVEN -> float2-aligned

__device__ __half gW[(size_t)E_*H_*F_];       // W1^T fp16 [e][n][k]
__device__ __half gX[(size_t)B_*F_];          // x fp16 [b][k]
__device__ float gPart[(size_t)E_*20*B_*KK];  // [e][nb][b][8]

__device__ __forceinline__ uint32_t smem_u32(const void* p){
    uint32_t a; asm("{ .reg .u64 t; cvta.to.shared.u64 t, %1; cvt.u32.u64 %0, t; }":"=r"(a):"l"(p)); return a;
}
#define CP16(dst,src) asm volatile("cp.async.cg.shared.global [%0], [%1], 16;"::"r"(dst),"l"(src):"memory")
#define LDM4(r,addr) asm volatile("ldmatrix.sync.aligned.m8n8.x4.shared.b16 {%0,%1,%2,%3}, [%4];" \
    : "=r"((r)[0]),"=r"((r)[1]),"=r"((r)[2]),"=r"((r)[3]) : "r"(addr))
__device__ __forceinline__ void mma_f16(float* c, const uint32_t* a, const uint32_t* b){
    asm volatile("mma.sync.aligned.m16n8k16.row.col.f32.f16.f16.f32 "
        "{%0,%1,%2,%3},{%4,%5,%6,%7},{%8,%9},{%0,%1,%2,%3};"
        : "+f"(c[0]),"+f"(c[1]),"+f"(c[2]),"+f"(c[3])
        : "r"(a[0]),"r"(a[1]),"r"(a[2]),"r"(a[3]),"r"(b[0]),"r"(b[1]));
}
__device__ __forceinline__ uint32_t pack2(float a, float b){
    __half2 h = __floats2half2_rn(a, b);
    return *reinterpret_cast<uint32_t*>(&h);
}

// ---- x -> fp16. 163840 float4s.
__global__ __launch_bounds__(256) void conv_x_kernel(const float* __restrict__ x){
    int i = blockIdx.x*256 + threadIdx.x;
    float4 v = ((const float4*)x)[i];
    uint2 o;
    o.x = pack2(v.x, v.y);
    o.y = pack2(v.z, v.w);
    ((uint2*)gX)[i] = o;
}

// ---- W1 [e][k][n] -> W1^T fp16 [e][n][k]. grid 3600.
__global__ __launch_bounds__(256) void conv_w1_kernel(const float* __restrict__ W1){
    __shared__ float s[64][129];
    int tile = blockIdx.x;
    int nb = tile % 20, kc = (tile/20) % 20, e = tile/400;
    const float* src = W1 + ((size_t)e*F_ + (size_t)kc*64)*H_ + (size_t)nb*128;
    for(int i=threadIdx.x; i<64*128; i+=256){
        int kk = i>>7, r = i&127;
        s[kk][r] = src[(size_t)kk*H_ + r];
    }
    __syncthreads();
    int kg = threadIdx.x & 7;
    int rbase = threadIdx.x >> 3;
#pragma unroll
    for(int u=0; u<4; u++){
        int row = u*32 + rbase;
        uint4 o;
        o.x = pack2(s[kg*8+0][row], s[kg*8+1][row]);
        o.y = pack2(s[kg*8+2][row], s[kg*8+3][row]);
        o.z = pack2(s[kg*8+4][row], s[kg*8+5][row]);
        o.w = pack2(s[kg*8+6][row], s[kg*8+7][row]);
        size_t off = (size_t)e*H_*F_ + (size_t)(nb*128+row)*F_ + kc*64 + kg*8;
        *(uint4*)(gW+off) = o;
    }
}

// ---- GEMM1 + fused bias/ReLU + GEMM2 partials.
// grid (2 mb, 20 nb, 9 e) = 360 CTAs, 512 threads.
// CTA tile 256x128; warp grid 8(m) x 2(n); warp tile 32x64.
__global__ __launch_bounds__(512,1) void gemm_kernel(const float* __restrict__ W2,
                                                     const float* __restrict__ b1){
    extern __shared__ char dyn[];
    __shared__ float w2s[128*8];
    __shared__ float biass[128];

    const int tid = threadIdx.x, lane = tid & 31, wid = tid >> 5;
    const int warp_m = wid & 7, warp_n = wid >> 3;
    const int m0 = blockIdx.x*256, n0 = blockIdx.y*128, e = blockIdx.z;
    const uint32_t dynU = smem_u32(dyn);

    if(tid < 256) ((float4*)w2s)[tid] = ((const float4*)(W2 + ((size_t)e*H_ + n0)*KK))[tid];
    if(tid < 32)  ((float4*)biass)[tid] = ((const float4*)(b1 + (size_t)e*H_ + n0))[tid];

    const int seg = tid & 7;
    const __half* gA = gX + (size_t)m0*F_;
    const __half* gB = gW + ((size_t)e*H_ + n0)*F_;
    const int ar0 = tid>>3, ar1 = (tid+512)>>3, ar2 = (tid+1024)>>3, ar3 = (tid+1536)>>3;
    const int br0 = tid>>3, br1 = (tid+512)>>3;

    uint32_t stB[NSTG];
#pragma unroll
    for(int s=0;s<NSTG;s++) stB[s] = dynU + s*STAGE_BYTES;

#define ISSUE(c) do{ \
    uint32_t st_ = stB[(c)%NSTG]; int ko_ = (c)*CH + seg*8; \
    CP16(st_+A_OFF + ar0*ROWB + seg*16, gA + (size_t)ar0*F_ + ko_); \
    CP16(st_+A_OFF + ar1*ROWB + seg*16, gA + (size_t)ar1*F_ + ko_); \
    CP16(st_+A_OFF + ar2*ROWB + seg*16, gA + (size_t)ar2*F_ + ko_); \
    CP16(st_+A_OFF + ar3*ROWB + seg*16, gA + (size_t)ar3*F_ + ko_); \
    CP16(st_+B_OFF + br0*ROWB + seg*16, gB + (size_t)br0*F_ + ko_); \
    CP16(st_+B_OFF + br1*ROWB + seg*16, gB + (size_t)br1*F_ + ko_); \
    asm volatile("cp.async.commit_group;":::"memory"); }while(0)

    const uint32_t aBase = A_OFF + (uint32_t)(warp_m*32 + (lane & 15))*ROWB + ((lane>>4)<<3)*2;
    const uint32_t bBase = B_OFF + (uint32_t)(warp_n*64 + ((lane>>4)&1)*8 + (lane&7))*ROWB + (((lane>>3)&1)<<3)*2;

    float acc[2][8][4];
#pragma unroll
    for(int a=0;a<2;a++)
#pragma unroll
    for(int b=0;b<8;b++)
#pragma unroll
    for(int d=0;d<4;d++) acc[a][b][d]=0.f;

    ISSUE(0); ISSUE(1);
    for(int c=0;c<NCH;c++){
        asm volatile("cp.async.wait_group 1;":::"memory");
        __syncthreads();
        if(c+2<NCH) ISSUE(c+2);
        const uint32_t st = stB[c%NSTG];
        const uint32_t ab = st + aBase, bb = st + bBase;
#pragma unroll
        for(int ks=0; ks<4; ks++){
            uint32_t ah[2][4], bh[4][4];
#pragma unroll
            for(int mi=0; mi<2; mi++)
                LDM4(ah[mi], ab + mi*16*ROWB + ks*32);
#pragma unroll
            for(int nj=0; nj<4; nj++)
                LDM4(bh[nj], bb + nj*16*ROWB + ks*32);
#pragma unroll
            for(int mi=0; mi<2; mi++)
#pragma unroll
            for(int ni=0; ni<8; ni++)
                mma_f16(acc[mi][ni], ah[mi], &bh[ni>>1][(ni&1)*2]);
        }
    }
#undef ISSUE
    __syncthreads();

    // epilogue: bias + ReLU -> htile [256][HTS]
    float* ht = (float*)dyn;
    const int g = lane >> 2, tg2 = (lane & 3)*2;
#pragma unroll
    for(int mi=0; mi<2; mi++){
        int r0 = warp_m*32 + mi*16 + g;
#pragma unroll
        for(int ni=0; ni<8; ni++){
            int c0 = warp_n*64 + ni*8 + tg2;
            float2 v0, v1;
            v0.x = fmaxf(acc[mi][ni][0] + biass[c0],   0.f);
            v0.y = fmaxf(acc[mi][ni][1] + biass[c0+1], 0.f);
            v1.x = fmaxf(acc[mi][ni][2] + biass[c0],   0.f);
            v1.y = fmaxf(acc[mi][ni][3] + biass[c0+1], 0.f);
            *(float2*)&ht[(size_t)r0*HTS + c0]     = v0;
            *(float2*)&ht[(size_t)(r0+8)*HTS + c0] = v1;
        }
    }
    __syncthreads();

    // GEMM2 partials: 512 threads -> 256 rows x 2 halves of 64 cols
    {
        const int row = tid >> 1, q = tid & 1;
        const float* hp = &ht[(size_t)row*HTS + q*64];
        const float* wp = &w2s[q*64*8];
        float pl[8];
#pragma unroll
        for(int k=0;k<8;k++) pl[k]=0.f;
#pragma unroll
        for(int cc=0; cc<64; cc++){
            int cr = (cc + q*9) & 63;               // rotate: decorrelate q0/q1 banks
            float h = hp[cr];
            const float4* w4 = (const float4*)&wp[cr*8];
            float4 wa = w4[0], wb = w4[1];
            pl[0]=fmaf(h,wa.x,pl[0]); pl[1]=fmaf(h,wa.y,pl[1]);
            pl[2]=fmaf(h,wa.z,pl[2]); pl[3]=fmaf(h,wa.w,pl[3]);
            pl[4]=fmaf(h,wb.x,pl[4]); pl[5]=fmaf(h,wb.y,pl[5]);
            pl[6]=fmaf(h,wb.z,pl[6]); pl[7]=fmaf(h,wb.w,pl[7]);
        }
#pragma unroll
        for(int k=0;k<8;k++) pl[k] += __shfl_xor_sync(0xFFFFFFFFu, pl[k], 1);
        float* dst = gPart + (((size_t)e*20 + blockIdx.y)*B_ + (m0+row))*KK + q*4;
        *(float4*)dst = make_float4(pl[q*4], pl[q*4+1], pl[q*4+2], pl[q*4+3]);
    }
}

// ---- tail: sum 20 partials per (e,k), +b2, softmax, path products
__global__ __launch_bounds__(256) void tail_kernel(const float* __restrict__ b2,
                                                   float* __restrict__ out){
    const int b = blockIdx.x, tid = threadIdx.x;
    __shared__ float part[180][8];
    __shared__ float logits_s[9][8];
    __shared__ float probs_s[9][8];
    for(int t=tid; t<180; t+=256){
        const float4* src = (const float4*)(gPart + ((size_t)t*B_ + b)*KK);
        *(float4*)&part[t][0] = src[0];
        *(float4*)&part[t][4] = src[1];
    }
    __syncthreads();
    if(tid < 72){
        int e = tid>>3, k = tid&7;
        float s = 0.f;
#pragma unroll
        for(int j=0;j<20;j++) s += part[e*20+j][k];
        float lv = s + b2[tid];
        logits_s[e][k] = lv;
        out[(size_t)B_*73 + ((size_t)e*B_ + b)*KK + k] = lv;
    }
    __syncthreads();
    if(tid < 9){
        float m = -INFINITY;
#pragma unroll
        for(int k=0;k<8;k++) m = fmaxf(m, logits_s[tid][k]);
        float ex[8], s = 0.f;
#pragma unroll
        for(int k=0;k<8;k++){ ex[k] = expf(logits_s[tid][k]-m); s += ex[k]; }
        float inv = 1.f/s;
#pragma unroll
        for(int k=0;k<8;k++) probs_s[tid][k] = ex[k]*inv;
    }
    __syncthreads();
    if(tid < 73){
        float v;
        if(tid==0) v = 1.f;
        else if(tid<9) v = probs_s[0][tid-1];
        else { int t = tid-9; v = probs_s[0][t>>3]*probs_s[1+(t>>3)][t&7]; }
        out[(size_t)b*73 + tid] = v;
    }
}

extern "C" void kernel_launch(void* const* d_in, const int* in_sizes, int n_in,
                              void* d_out, int out_size){
    const float* x  = (const float*)d_in[0];
    const float* W1 = (const float*)d_in[1];
    const float* b1 = (const float*)d_in[2];
    const float* W2 = (const float*)d_in[3];
    const float* b2 = (const float*)d_in[4];
    float* out = (float*)d_out;

    cudaFuncSetAttribute(gemm_kernel, cudaFuncAttributeMaxDynamicSharedMemorySize, DYN_BYTES);

    conv_x_kernel<<<640, 256>>>(x);
    conv_w1_kernel<<<3600, 256>>>(W1);
    dim3 grid(2, 20, 9);
    gemm_kernel<<<grid, 512, DYN_BYTES>>>(W2, b1);
    tail_kernel<<<B_, 256>>>(b2, out);
}

// round 9
// speedup vs baseline: 5.5093x; 1.1875x over previous
#include <cuda_runtime.h>
#include <cuda_fp16.h>
#include <math.h>
#include <stdint.h>

#define B_  512
#define F_  1280
#define H_  2560
#define KK  8
#define E_  9

#define CH   64                     // k per chunk
#define NCH  (F_/CH)                // 20
#define SAE  72                     // padded row stride (fp16) -> 144B
#define ROWB (SAE*2)                // 144
#define ABUF_BYTES (128*ROWB)       // 18432
#define BBUF_BYTES (128*ROWB)       // 18432
#define STAGE_BYTES (ABUF_BYTES+BBUF_BYTES)  // 36864
#define A_OFF 0
#define B_OFF ABUF_BYTES
#define NSTG 3
#define DYN_BYTES (NSTG*STAGE_BYTES)  // 110592 -> 2 CTAs/SM
#define HTS 130                     // htile row stride (floats), even
// epilogue dyn layout: htile [128][130] = 66560B, then w2s 4096B, bias 512B
#define EP_W2_OFF  66560
#define EP_B1_OFF  70656

__device__ __half gW[(size_t)E_*H_*F_];       // W1^T fp16 [e][n][k]
__device__ __half gX[(size_t)B_*F_];          // x fp16 [b][k]
__device__ float gPart[(size_t)E_*20*B_*KK];  // [e][nb][b][8]

__device__ __forceinline__ uint32_t smem_u32(const void* p){
    uint32_t a; asm("{ .reg .u64 t; cvta.to.shared.u64 t, %1; cvt.u32.u64 %0, t; }":"=r"(a):"l"(p)); return a;
}
#define CP16(dst,src) asm volatile("cp.async.cg.shared.global [%0], [%1], 16;"::"r"(dst),"l"(src):"memory")
#define LDM4(r,addr) asm volatile("ldmatrix.sync.aligned.m8n8.x4.shared.b16 {%0,%1,%2,%3}, [%4];" \
    : "=r"((r)[0]),"=r"((r)[1]),"=r"((r)[2]),"=r"((r)[3]) : "r"(addr))
__device__ __forceinline__ void mma_f16(float* c, const uint32_t* a, const uint32_t* b){
    asm volatile("mma.sync.aligned.m16n8k16.row.col.f32.f16.f16.f32 "
        "{%0,%1,%2,%3},{%4,%5,%6,%7},{%8,%9},{%0,%1,%2,%3};"
        : "+f"(c[0]),"+f"(c[1]),"+f"(c[2]),"+f"(c[3])
        : "r"(a[0]),"r"(a[1]),"r"(a[2]),"r"(a[3]),"r"(b[0]),"r"(b[1]));
}
__device__ __forceinline__ uint32_t pack2(float a, float b){
    __half2 h = __floats2half2_rn(a, b);
    return *reinterpret_cast<uint32_t*>(&h);
}

// ---- x -> fp16. 163840 float4s.
__global__ __launch_bounds__(256) void conv_x_kernel(const float* __restrict__ x){
    int i = blockIdx.x*256 + threadIdx.x;
    float4 v = ((const float4*)x)[i];
    uint2 o;
    o.x = pack2(v.x, v.y);
    o.y = pack2(v.z, v.w);
    ((uint2*)gX)[i] = o;
}

// ---- W1 [e][k][n] -> W1^T fp16 [e][n][k]. grid 3600.
__global__ __launch_bounds__(256) void conv_w1_kernel(const float* __restrict__ W1){
    __shared__ float s[64][129];
    int tile = blockIdx.x;
    int nb = tile % 20, kc = (tile/20) % 20, e = tile/400;
    const float* src = W1 + ((size_t)e*F_ + (size_t)kc*64)*H_ + (size_t)nb*128;
    for(int i=threadIdx.x; i<64*128; i+=256){
        int kk = i>>7, r = i&127;
        s[kk][r] = src[(size_t)kk*H_ + r];
    }
    __syncthreads();
    int kg = threadIdx.x & 7;
    int rbase = threadIdx.x >> 3;
#pragma unroll
    for(int u=0; u<4; u++){
        int row = u*32 + rbase;
        uint4 o;
        o.x = pack2(s[kg*8+0][row], s[kg*8+1][row]);
        o.y = pack2(s[kg*8+2][row], s[kg*8+3][row]);
        o.z = pack2(s[kg*8+4][row], s[kg*8+5][row]);
        o.w = pack2(s[kg*8+6][row], s[kg*8+7][row]);
        size_t off = (size_t)e*H_*F_ + (size_t)(nb*128+row)*F_ + kc*64 + kg*8;
        *(uint4*)(gW+off) = o;
    }
}

// ---- GEMM1 + fused bias/ReLU + GEMM2 partials.
// grid (4 mb, 20 nb, 9 e) = 720 CTAs, 256 threads, 2 CTAs/SM.
// CTA tile 128x128; warp grid 4(m) x 2(n); warp tile 32x64.
__global__ __launch_bounds__(256,2) void gemm_kernel(const float* __restrict__ W2,
                                                     const float* __restrict__ b1){
    extern __shared__ char dyn[];
    const int tid = threadIdx.x, lane = tid & 31, wid = tid >> 5;
    const int warp_m = wid & 3, warp_n = wid >> 2;
    const int m0 = blockIdx.x*128, n0 = blockIdx.y*128, e = blockIdx.z;
    const uint32_t dynU = smem_u32(dyn);

    // cp.async mapping: per buffer 128 rows x 8 segs of 16B = 1024 tasks, 4/thread each for A and B
    const int seg = tid & 7;
    const __half* gA = gX + (size_t)m0*F_;
    const __half* gB = gW + ((size_t)e*H_ + n0)*F_;
    const int r0 = tid>>3, r1 = (tid+256)>>3, r2 = (tid+512)>>3, r3 = (tid+768)>>3;

    uint32_t stB[NSTG];
#pragma unroll
    for(int s=0;s<NSTG;s++) stB[s] = dynU + s*STAGE_BYTES;

#define ISSUE(c) do{ \
    uint32_t st_ = stB[(c)%NSTG]; int ko_ = (c)*CH + seg*8; \
    CP16(st_+A_OFF + r0*ROWB + seg*16, gA + (size_t)r0*F_ + ko_); \
    CP16(st_+A_OFF + r1*ROWB + seg*16, gA + (size_t)r1*F_ + ko_); \
    CP16(st_+A_OFF + r2*ROWB + seg*16, gA + (size_t)r2*F_ + ko_); \
    CP16(st_+A_OFF + r3*ROWB + seg*16, gA + (size_t)r3*F_ + ko_); \
    CP16(st_+B_OFF + r0*ROWB + seg*16, gB + (size_t)r0*F_ + ko_); \
    CP16(st_+B_OFF + r1*ROWB + seg*16, gB + (size_t)r1*F_ + ko_); \
    CP16(st_+B_OFF + r2*ROWB + seg*16, gB + (size_t)r2*F_ + ko_); \
    CP16(st_+B_OFF + r3*ROWB + seg*16, gB + (size_t)r3*F_ + ko_); \
    asm volatile("cp.async.commit_group;":::"memory"); }while(0)

    const uint32_t aBase = A_OFF + (uint32_t)(warp_m*32 + (lane & 15))*ROWB + ((lane>>4)<<3)*2;
    const uint32_t bBase = B_OFF + (uint32_t)(warp_n*64 + ((lane>>4)&1)*8 + (lane&7))*ROWB + (((lane>>3)&1)<<3)*2;

    float acc[2][8][4];
#pragma unroll
    for(int a=0;a<2;a++)
#pragma unroll
    for(int b=0;b<8;b++)
#pragma unroll
    for(int d=0;d<4;d++) acc[a][b][d]=0.f;

    ISSUE(0); ISSUE(1);
    for(int c=0;c<NCH;c++){
        asm volatile("cp.async.wait_group 1;":::"memory");
        __syncthreads();
        if(c+2<NCH) ISSUE(c+2);
        const uint32_t st = stB[c%NSTG];
        const uint32_t ab = st + aBase, bb = st + bBase;
#pragma unroll
        for(int ks=0; ks<4; ks++){
            uint32_t ah[2][4];
#pragma unroll
            for(int mi=0; mi<2; mi++)
                LDM4(ah[mi], ab + mi*16*ROWB + ks*32);
#pragma unroll
            for(int nj=0; nj<4; nj++){
                uint32_t bt[4];
                LDM4(bt, bb + nj*16*ROWB + ks*32);
#pragma unroll
                for(int mi=0; mi<2; mi++){
                    mma_f16(acc[mi][nj*2+0], ah[mi], &bt[0]);
                    mma_f16(acc[mi][nj*2+1], ah[mi], &bt[2]);
                }
            }
        }
    }
#undef ISSUE
    __syncthreads();

    // load W2 tile + bias into dyn smem (past htile region)
    float* w2s   = (float*)(dyn + EP_W2_OFF);
    float* biass = (float*)(dyn + EP_B1_OFF);
    ((float4*)w2s)[tid] = ((const float4*)(W2 + ((size_t)e*H_ + n0)*KK))[tid];
    if(tid < 32) ((float4*)biass)[tid] = ((const float4*)(b1 + (size_t)e*H_ + n0))[tid];
    __syncthreads();

    // epilogue: bias + ReLU -> htile [128][HTS]
    float* ht = (float*)dyn;
    const int g = lane >> 2, tg2 = (lane & 3)*2;
#pragma unroll
    for(int mi=0; mi<2; mi++){
        int rr = warp_m*32 + mi*16 + g;
#pragma unroll
        for(int ni=0; ni<8; ni++){
            int c0 = warp_n*64 + ni*8 + tg2;
            float2 v0, v1;
            v0.x = fmaxf(acc[mi][ni][0] + biass[c0],   0.f);
            v0.y = fmaxf(acc[mi][ni][1] + biass[c0+1], 0.f);
            v1.x = fmaxf(acc[mi][ni][2] + biass[c0],   0.f);
            v1.y = fmaxf(acc[mi][ni][3] + biass[c0+1], 0.f);
            *(float2*)&ht[(size_t)rr*HTS + c0]     = v0;
            *(float2*)&ht[(size_t)(rr+8)*HTS + c0] = v1;
        }
    }
    __syncthreads();

    // GEMM2 partials: 256 threads -> 128 rows x 2 halves of 64 cols
    {
        const int row = tid >> 1, q = tid & 1;
        const float* hp = &ht[(size_t)row*HTS + q*64];
        const float* wp = &w2s[q*64*8];
        float pl[8];
#pragma unroll
        for(int k=0;k<8;k++) pl[k]=0.f;
#pragma unroll
        for(int cc=0; cc<64; cc++){
            int cr = (cc + q*9) & 63;
            float h = hp[cr];
            const float4* w4 = (const float4*)&wp[cr*8];
            float4 wa = w4[0], wb = w4[1];
            pl[0]=fmaf(h,wa.x,pl[0]); pl[1]=fmaf(h,wa.y,pl[1]);
            pl[2]=fmaf(h,wa.z,pl[2]); pl[3]=fmaf(h,wa.w,pl[3]);
            pl[4]=fmaf(h,wb.x,pl[4]); pl[5]=fmaf(h,wb.y,pl[5]);
            pl[6]=fmaf(h,wb.z,pl[6]); pl[7]=fmaf(h,wb.w,pl[7]);
        }
#pragma unroll
        for(int k=0;k<8;k++) pl[k] += __shfl_xor_sync(0xFFFFFFFFu, pl[k], 1);
        float* dst = gPart + (((size_t)e*20 + blockIdx.y)*B_ + (m0+row))*KK + q*4;
        *(float4*)dst = make_float4(pl[q*4], pl[q*4+1], pl[q*4+2], pl[q*4+3]);
    }
}

// ---- tail: sum 20 partials per (e,k), +b2, softmax, path products
__global__ __launch_bounds__(256) void tail_kernel(const float* __restrict__ b2,
                                                   float* __restrict__ out){
    const int b = blockIdx.x, tid = threadIdx.x;
    __shared__ float part[180][8];
    __shared__ float logits_s[9][8];
    __shared__ float probs_s[9][8];
    for(int t=tid; t<180; t+=256){
        const float4* src = (const float4*)(gPart + ((size_t)t*B_ + b)*KK);
        *(float4*)&part[t][0] = src[0];
        *(float4*)&part[t][4] = src[1];
    }
    __syncthreads();
    if(tid < 72){
        int e = tid>>3, k = tid&7;
        float s = 0.f;
#pragma unroll
        for(int j=0;j<20;j++) s += part[e*20+j][k];
        float lv = s + b2[tid];
        logits_s[e][k] = lv;
        out[(size_t)B_*73 + ((size_t)e*B_ + b)*KK + k] = lv;
    }
    __syncthreads();
    if(tid < 9){
        float m = -INFINITY;
#pragma unroll
        for(int k=0;k<8;k++) m = fmaxf(m, logits_s[tid][k]);
        float ex[8], s = 0.f;
#pragma unroll
        for(int k=0;k<8;k++){ ex[k] = expf(logits_s[tid][k]-m); s += ex[k]; }
        float inv = 1.f/s;
#pragma unroll
        for(int k=0;k<8;k++) probs_s[tid][k] = ex[k]*inv;
    }
    __syncthreads();
    if(tid < 73){
        float v;
        if(tid==0) v = 1.f;
        else if(tid<9) v = probs_s[0][tid-1];
        else { int t = tid-9; v = probs_s[0][t>>3]*probs_s[1+(t>>3)][t&7]; }
        out[(size_t)b*73 + tid] = v;
    }
}

extern "C" void kernel_launch(void* const* d_in, const int* in_sizes, int n_in,
                              void* d_out, int out_size){
    const float* x  = (const float*)d_in[0];
    const float* W1 = (const float*)d_in[1];
    const float* b1 = (const float*)d_in[2];
    const float* W2 = (const float*)d_in[3];
    const float* b2 = (const float*)d_in[4];
    float* out = (float*)d_out;

    cudaFuncSetAttribute(gemm_kernel, cudaFuncAttributeMaxDynamicSharedMemorySize, DYN_BYTES);

    conv_x_kernel<<<640, 256>>>(x);
    conv_w1_kernel<<<3600, 256>>>(W1);
    dim3 grid(4, 20, 9);
    gemm_kernel<<<grid, 256, DYN_BYTES>>>(W2, b1);
    tail_kernel<<<B_, 256>>>(b2, out);
}